// round 11
// baseline (speedup 1.0000x reference)
#include <cuda_runtime.h>

#define O_TOTAL 16384

// Scratch: A[p][b] = (pz@W1_h)[b,h] * W2[h] (SIGNED), rows permuted so that
// all h with W2[h]>=0 come first. 32KB.
__device__ float g_Aw[128 * 64];

// ---------- packed f32x2 helpers ----------
__device__ __forceinline__ unsigned long long pack2(float x, float y) {
    unsigned long long u;
    asm("mov.b64 %0, {%1,%2};" : "=l"(u) : "f"(x), "f"(y));
    return u;
}
__device__ __forceinline__ void unpack2(unsigned long long u, float &x, float &y) {
    asm("mov.b64 {%0,%1}, %2;" : "=f"(x), "=f"(y) : "l"(u));
}
__device__ __forceinline__ unsigned long long add2(unsigned long long a, unsigned long long b) {
    unsigned long long d;
    asm("add.rn.f32x2 %0, %1, %2;" : "=l"(d) : "l"(a), "l"(b));
    return d;
}
__device__ __forceinline__ unsigned long long fma2(unsigned long long a, unsigned long long b, unsigned long long c) {
    unsigned long long d;
    asm("fma.rn.f32x2 %0, %1, %2, %3;" : "=l"(d) : "l"(a), "l"(b), "l"(c));
    return d;
}
// max(v,0) per-half: 2 scalar FMNMX; pack/unpack are register aliasing (elided)
__device__ __forceinline__ unsigned long long relu2(unsigned long long v) {
    float x, y;
    unpack2(v, x, y);
    return pack2(fmaxf(x, 0.0f), fmaxf(y, 0.0f));
}
// min(v,0) per-half
__device__ __forceinline__ unsigned long long nrelu2(unsigned long long v) {
    float x, y;
    unpack2(v, x, y);
    return pack2(fminf(x, 0.0f), fminf(y, 0.0f));
}

// Sign-partition rank for tid<128 (4 full warps). perm[h] = destination row.
// Positive (w>=0) h keep relative order in [0,npos); negative in [npos,128).
__device__ __forceinline__ void compute_perm(const float* W2, int tid,
                                             int* wcnt, int* perm_s, int* npos_s)
{
    unsigned m = 0; bool pos = false;
    if (tid < 128) {
        float w = W2[tid];
        pos = (w >= 0.0f);
        m = __ballot_sync(0xffffffffu, pos);
        if ((tid & 31) == 0) wcnt[tid >> 5] = __popc(m);
    }
    __syncthreads();
    if (tid < 128) {
        int wd = tid >> 5, ln = tid & 31;
        int c0 = wcnt[0], c1 = wcnt[1], c2 = wcnt[2], c3 = wcnt[3];
        int npos = c0 + c1 + c2 + c3;
        int pb = 0;
        if (wd > 0) pb += c0;
        if (wd > 1) pb += c1;
        if (wd > 2) pb += c2;
        unsigned lm = (1u << ln) - 1u;
        int r = pos ? (pb + __popc(m & lm))
                    : (npos + wd * 32 - pb + __popc((~m) & lm));
        perm_s[tid] = r;
        if (tid == 0) *npos_s = npos;
    }
    __syncthreads();
}

// =====================================================================
// Kernel A: 16 CTAs x 512. pz = relu(z@Wz+bz) (redundant per CTA),
// then 8 h-rows: g_Aw[perm[h], b] = (pz@W1_h)[b,h] * W2[h] (signed).
// =====================================================================
// floats: zs[0,2048) Wzs[2048,6144) bzs[6144,6272) pzT[6272,14592)
//         perm[14592..14720) wcnt[14720..14724) npos[14724]
#define A_SMEM (14728 * 4)

__global__ void __launch_bounds__(512) k_A(
    const float* __restrict__ z,  const float* __restrict__ Wz,
    const float* __restrict__ bz, const float* __restrict__ W1,
    const float* __restrict__ W2)
{
    extern __shared__ float sm[];
    float* zs  = sm;
    float* Wzs = sm + 2048;
    float* bzs = sm + 6144;
    float* pzT = sm + 6272;            // [h][b] pitch 65
    int* perm_s = (int*)(sm + 14592);
    int* wcnt   = (int*)(sm + 14720);
    int* npos_s = (int*)(sm + 14724);

    int tid = threadIdx.x;
    int cta = blockIdx.x;

    for (int i = tid; i < 2048; i += 512) zs[i]  = z[i];
    for (int i = tid; i < 4096; i += 512) Wzs[i] = Wz[i];
    if (tid < 128) bzs[tid] = bz[tid];

    compute_perm(W2, tid, wcnt, perm_s, npos_s);   // includes 2 syncthreads

    // pz phase: thread -> b = tid>>3, 16 h outputs starting at (tid&7)*16
    {
        int b  = tid >> 3;
        int h0 = (tid & 7) * 16;
        float acc[16];
#pragma unroll
        for (int j = 0; j < 16; j++) acc[j] = bzs[h0 + j];

#pragma unroll 4
        for (int k = 0; k < 32; k++) {
            float zv = zs[b * 32 + k];
            const float4* wrow = (const float4*)(Wzs + k * 128 + h0);
            float4 w0 = wrow[0], w1 = wrow[1], w2 = wrow[2], w3 = wrow[3];
            acc[0]  += zv * w0.x;  acc[1]  += zv * w0.y;
            acc[2]  += zv * w0.z;  acc[3]  += zv * w0.w;
            acc[4]  += zv * w1.x;  acc[5]  += zv * w1.y;
            acc[6]  += zv * w1.z;  acc[7]  += zv * w1.w;
            acc[8]  += zv * w2.x;  acc[9]  += zv * w2.y;
            acc[10] += zv * w2.z;  acc[11] += zv * w2.w;
            acc[12] += zv * w3.x;  acc[13] += zv * w3.y;
            acc[14] += zv * w3.z;  acc[15] += zv * w3.w;
        }
#pragma unroll
        for (int j = 0; j < 16; j++)
            pzT[(h0 + j) * 65 + b] = fmaxf(acc[j], 0.0f);
    }
    __syncthreads();

    // A phase: h = cta*8 + (tid>>6), b = tid&63
    {
        int h = cta * 8 + (tid >> 6);
        int b = tid & 63;
        float a = 0.0f;
#pragma unroll 8
        for (int k = 0; k < 128; k++)
            a += pzT[k * 65 + b] * W1[k * 128 + h];
        g_Aw[perm_s[h] * 64 + b] = a * W2[h];   // signed scale, permuted row
    }
    cudaTriggerProgrammaticLaunchCompletion();
}

// =====================================================================
// Kernel main: 256 CTAs x 512 thr, 2 CTAs/SM. CTA t: o-tile [t*64,+64).
//  prolog: Gd[p][o] dup pairs = (fe@W1_f + fb*W1_b + b1)*W2[h], row perm[h]
//  (overlapped with k_A via PDL), then As <- g_Aw.
//  main: out[b,o] = sum_{p<npos} max(A+G,0) + sum_{p>=npos} min(A+G,0) + b2
// =====================================================================
// floats: As[0,8192)  Gd(ull)[8192,24576)  W1b_s[24576) b1_s[24704)
//         ws_s[24832) perm[24960..25088) wcnt[25088..25092) npos[25092]
// staging overlay inside As: W1fs[0,4096) fes[4096,6176)
#define MAIN_SMEM (25096 * 4)   // 100384

__global__ void __launch_bounds__(512, 2) k_main(
    const float* __restrict__ fe, const float* __restrict__ fb,
    const float* __restrict__ W1, const float* __restrict__ b1,
    const float* __restrict__ W2, const float* __restrict__ b2,
    float* __restrict__ out)
{
    extern __shared__ float sm[];
    float* As = sm;                                            // [p][64]
    unsigned long long* Gd = (unsigned long long*)(sm + 8192); // [p][64] dup pairs
    float* W1b_s = sm + 24576;
    float* b1_s  = sm + 24704;
    float* ws_s  = sm + 24832;                                 // signed w
    int* perm_s  = (int*)(sm + 24960);
    int* wcnt    = (int*)(sm + 25088);
    int* npos_s  = (int*)(sm + 25092);
    // staging overlay
    float* W1fs = sm;             // [c][h] 32x128
    float* fes  = sm + 4096;      // [c][o] pitch 65

    int tid = threadIdx.x;
    int t = blockIdx.x;

    // ---- stage ----
    for (int i = tid; i < 4096; i += 512) W1fs[i] = W1[128 * 128 + i];
    for (int i = tid; i < 2048; i += 512) {
        int o = i >> 5, c = i & 31;
        fes[c * 65 + o] = fe[(t * 64 + o) * 32 + c];
    }
    if (tid < 128) {
        W1b_s[tid] = W1[160 * 128 + tid];
        b1_s[tid]  = b1[tid];
        ws_s[tid]  = W2[tid];
    }
    compute_perm(W2, tid, wcnt, perm_s, npos_s);   // includes 2 syncthreads

    // ---- G tile GEMM (64o x 128h x 32c), epilogue permuted + signed scale ----
    {
        int o  = tid & 63;
        int hc = tid >> 6;                 // 0..7 -> 16 h each
        unsigned long long acc[8];
#pragma unroll
        for (int j = 0; j < 8; j++) acc[j] = 0ull;

#pragma unroll 4
        for (int c = 0; c < 32; c++) {
            float f = fes[c * 65 + o];
            unsigned long long f2 = pack2(f, f);
            const unsigned long long* wrow =
                (const unsigned long long*)(W1fs + c * 128 + hc * 16);
#pragma unroll
            for (int j = 0; j < 8; j++)
                acc[j] = fma2(f2, wrow[j], acc[j]);
        }

        float fbv = fb[t * 64 + o];
#pragma unroll
        for (int j = 0; j < 8; j++) {
            int h0 = hc * 16 + 2 * j;
            float ax, ay;
            unpack2(acc[j], ax, ay);
            float g0 = (ax + fbv * W1b_s[h0]     + b1_s[h0])     * ws_s[h0];
            float g1 = (ay + fbv * W1b_s[h0 + 1] + b1_s[h0 + 1]) * ws_s[h0 + 1];
            Gd[perm_s[h0] * 64 + o]     = pack2(g0, g0);
            Gd[perm_s[h0 + 1] * 64 + o] = pack2(g1, g1);
        }
    }
    __syncthreads();    // staging reads done; Gd complete

    // ---- wait for k_A (PDL), then fill As ----
    cudaGridDependencySynchronize();
    for (int i = tid; i < 2048; i += 512)
        ((float4*)As)[i] = ((const float4*)g_Aw)[i];
    __syncthreads();

    // ---- main loop: thread tile 4b x 2o ----
    int og = tid & 31;            // o0 = og*2
    int bg = tid >> 5;            // b0 = bg*4 (warp-uniform)
    int o0 = og * 2, b0 = bg * 4;
    int npos = *npos_s;

    const ulonglong2* Av = (const ulonglong2*)As;   // [p*16 + bg]
    const ulonglong2* Gv = (const ulonglong2*)Gd;   // [p*32 + og]

    unsigned long long acc00 = 0ull, acc01 = 0ull, acc10 = 0ull, acc11 = 0ull;

    int h = 0;
#pragma unroll 4
    for (; h < npos; h++) {
        ulonglong2 ap = Av[h * 16 + bg];
        ulonglong2 gp = Gv[h * 32 + og];
        acc00 = add2(acc00, relu2(add2(ap.x, gp.x)));
        acc01 = add2(acc01, relu2(add2(ap.x, gp.y)));
        acc10 = add2(acc10, relu2(add2(ap.y, gp.x)));
        acc11 = add2(acc11, relu2(add2(ap.y, gp.y)));
    }
#pragma unroll 4
    for (; h < 128; h++) {
        ulonglong2 ap = Av[h * 16 + bg];
        ulonglong2 gp = Gv[h * 32 + og];
        acc00 = add2(acc00, nrelu2(add2(ap.x, gp.x)));
        acc01 = add2(acc01, nrelu2(add2(ap.x, gp.y)));
        acc10 = add2(acc10, nrelu2(add2(ap.y, gp.x)));
        acc11 = add2(acc11, nrelu2(add2(ap.y, gp.y)));
    }

    float b2v = b2[0];
    float* obase = out + t * 64 + o0;
    float x0, x1, y0, y1;
    unpack2(acc00, x0, x1);   // (b0,o0),(b1,o0)
    unpack2(acc01, y0, y1);   // (b0,o1),(b1,o1)
    *(float2*)(obase + (b0 + 0) * O_TOTAL) = make_float2(x0 + b2v, y0 + b2v);
    *(float2*)(obase + (b0 + 1) * O_TOTAL) = make_float2(x1 + b2v, y1 + b2v);
    unpack2(acc10, x0, x1);   // (b2,o0),(b3,o0)
    unpack2(acc11, y0, y1);   // (b2,o1),(b3,o1)
    *(float2*)(obase + (b0 + 2) * O_TOTAL) = make_float2(x0 + b2v, y0 + b2v);
    *(float2*)(obase + (b0 + 3) * O_TOTAL) = make_float2(x1 + b2v, y1 + b2v);
}

extern "C" void kernel_launch(void* const* d_in, const int* in_sizes, int n_in,
                              void* d_out, int out_size) {
    (void)in_sizes; (void)n_in; (void)out_size;
    const float* z  = (const float*)d_in[0];
    const float* fe = (const float*)d_in[1];
    const float* fb = (const float*)d_in[2];
    const float* Wz = (const float*)d_in[3];
    const float* bz = (const float*)d_in[4];
    const float* W1 = (const float*)d_in[5];
    const float* b1 = (const float*)d_in[6];
    const float* W2 = (const float*)d_in[7];
    const float* b2 = (const float*)d_in[8];
    float* out = (float*)d_out;

    cudaFuncSetAttribute(k_A,    cudaFuncAttributeMaxDynamicSharedMemorySize, A_SMEM);
    cudaFuncSetAttribute(k_main, cudaFuncAttributeMaxDynamicSharedMemorySize, MAIN_SMEM);

    k_A<<<16, 512, A_SMEM>>>(z, Wz, bz, W1, W2);

    // PDL launch of k_main: starts while k_A runs; syncs before reading g_Aw.
    cudaLaunchConfig_t cfg = {};
    cfg.gridDim = dim3(256);
    cfg.blockDim = dim3(512);
    cfg.dynamicSmemBytes = MAIN_SMEM;
    cfg.stream = 0;
    cudaLaunchAttribute attrs[1];
    attrs[0].id = cudaLaunchAttributeProgrammaticStreamSerialization;
    attrs[0].val.programmaticStreamSerializationAllowed = 1;
    cfg.attrs = attrs;
    cfg.numAttrs = 1;
    cudaLaunchKernelEx(&cfg, k_main, fe, fb, W1, b1, W2, b2, out);
}